// round 16
// baseline (speedup 1.0000x reference)
#include <cuda_runtime.h>
#include <cuda_bf16.h>
#include <cstdint>

#define N_NODES 100000
#define N_EDGES 1600000
#define KTOT 384
#define SCAN_CHUNKS ((N_NODES + 1023) / 1024)   // 98

// ---------------------------------------------------------------------------
// Device-global scratch
__device__ float g_P[(size_t)N_NODES * 192];            // layer-2 transformed
__device__ __nv_bfloat16 g_X_hi[(size_t)N_NODES * 128]; // x pre-split
__device__ __nv_bfloat16 g_X_lo[(size_t)N_NODES * 128];
__device__ __nv_bfloat16 g_AGG_hi[(size_t)N_NODES * 256]; // A0|A1 mean-scaled, pre-split
__device__ __nv_bfloat16 g_AGG_lo[(size_t)N_NODES * 256];
__device__ __nv_bfloat16 g_H_hi[(size_t)N_NODES * 128];
__device__ __nv_bfloat16 g_H_lo[(size_t)N_NODES * 128];
__device__ __nv_bfloat16 g_W1T_hi[128 * KTOT];
__device__ __nv_bfloat16 g_W1T_lo[128 * KTOT];
__device__ __nv_bfloat16 g_W2T_hi[192 * 128];
__device__ __nv_bfloat16 g_W2T_lo[192 * 128];
__device__ int g_deg[N_NODES];
__device__ int g_offs[N_NODES];
__device__ int g_epos[N_EDGES];
__device__ int g_part[SCAN_CHUNKS];
__device__ int g_csr[N_EDGES];                          // src | (rel<<30), grouped by dst

// ---------------------------------------------------------------------------
__device__ __forceinline__ unsigned pack2(__nv_bfloat16 a, __nv_bfloat16 b) {
    union { __nv_bfloat162 v; unsigned u; } c;
    c.v = __halves2bfloat162(a, b);
    return c.u;
}

__device__ __forceinline__ void split4(const float4 v,
                                       unsigned& hi0, unsigned& hi1,
                                       unsigned& lo0, unsigned& lo1) {
    __nv_bfloat16 h0 = __float2bfloat16(v.x), h1 = __float2bfloat16(v.y);
    __nv_bfloat16 h2 = __float2bfloat16(v.z), h3 = __float2bfloat16(v.w);
    __nv_bfloat16 l0 = __float2bfloat16(v.x - __bfloat162float(h0));
    __nv_bfloat16 l1 = __float2bfloat16(v.y - __bfloat162float(h1));
    __nv_bfloat16 l2 = __float2bfloat16(v.z - __bfloat162float(h2));
    __nv_bfloat16 l3 = __float2bfloat16(v.w - __bfloat162float(h3));
    hi0 = pack2(h0, h1); hi1 = pack2(h2, h3);
    lo0 = pack2(l0, l1); lo1 = pack2(l2, l3);
}

// ---------------------------------------------------------------------------
__global__ void __launch_bounds__(256)
prep_w_kernel(const float* __restrict__ W1_rel,
              const float* __restrict__ W1_root,
              const float* __restrict__ W2_rel,
              const float* __restrict__ W2_root) {
    int i = blockIdx.x * blockDim.x + threadIdx.x;
    const int SZ1 = 128 * KTOT;
    const int SZ2 = 192 * 128;
    if (i >= SZ1 + SZ2) return;
    float v;
    __nv_bfloat16 *dh, *dl;
    if (i < SZ1) {
        int n = i / KTOT, k = i % KTOT;
        if (k < 128) v = W1_root[k * 128 + n];
        else {
            int r = (k - 128) >> 7, kk = (k - 128) & 127;
            v = W1_rel[(size_t)r * 128 * 128 + kk * 128 + n];
        }
        dh = g_W1T_hi + i; dl = g_W1T_lo + i;
    } else {
        int j = i - SZ1;
        int n = j / 128, k = j % 128;
        if (n < 64)       v = W2_root[k * 64 + n];
        else if (n < 128) v = W2_rel[(size_t)0 * 128 * 64 + k * 64 + (n - 64)];
        else              v = W2_rel[(size_t)1 * 128 * 64 + k * 64 + (n - 128)];
        dh = g_W2T_hi + j; dl = g_W2T_lo + j;
    }
    __nv_bfloat16 h = __float2bfloat16(v);
    *dh = h;
    *dl = __float2bfloat16(v - __bfloat162float(h));
}

// Pre-split x into bf16 hi/lo
__global__ void __launch_bounds__(256)
prep_x_kernel(const float* __restrict__ x,
              __nv_bfloat16* __restrict__ Xh, __nv_bfloat16* __restrict__ Xl) {
    int i = blockIdx.x * blockDim.x + threadIdx.x;      // over N*32 float4
    if (i >= N_NODES * 32) return;
    float4 v = ((const float4*)x)[i];
    unsigned h0, h1, l0, l1;
    split4(v, h0, h1, l0, l1);
    ((uint2*)Xh)[i] = make_uint2(h0, h1);
    ((uint2*)Xl)[i] = make_uint2(l0, l1);
}

// ---------------------------------------------------------------------------
// CSR construction
__global__ void __launch_bounds__(256)
deg_kernel(const int* __restrict__ ei, int* __restrict__ deg, int* __restrict__ epos) {
    int e = blockIdx.x * blockDim.x + threadIdx.x;
    if (e < N_EDGES) epos[e] = atomicAdd(&deg[ei[N_EDGES + e]], 1);
}

__global__ void __launch_bounds__(1024)
scan_partial_kernel(const int* __restrict__ deg, int* __restrict__ part) {
    __shared__ int red[32];
    int idx = blockIdx.x * 1024 + threadIdx.x;
    int v = (idx < N_NODES) ? deg[idx] : 0;
#pragma unroll
    for (int o = 16; o; o >>= 1) v += __shfl_xor_sync(0xFFFFFFFFu, v, o);
    if ((threadIdx.x & 31) == 0) red[threadIdx.x >> 5] = v;
    __syncthreads();
    if (threadIdx.x < 32) {
        int s = red[threadIdx.x];
#pragma unroll
        for (int o = 16; o; o >>= 1) s += __shfl_xor_sync(0xFFFFFFFFu, s, o);
        if (threadIdx.x == 0) part[blockIdx.x] = s;
    }
}

__global__ void __launch_bounds__(128)
scan_part_kernel(int* __restrict__ part) {
    __shared__ int buf[SCAN_CHUNKS];
    int t = threadIdx.x;
    if (t < SCAN_CHUNKS) buf[t] = part[t];
    __syncthreads();
    if (t == 0) {
        int run = 0;
        for (int i = 0; i < SCAN_CHUNKS; i++) {
            int v = buf[i];
            buf[i] = run;
            run += v;
        }
    }
    __syncthreads();
    if (t < SCAN_CHUNKS) part[t] = buf[t];
}

__global__ void __launch_bounds__(1024)
scan_final_kernel(const int* __restrict__ deg, const int* __restrict__ part,
                  int* __restrict__ offs) {
    __shared__ int warpsum[32];
    int t = threadIdx.x;
    int idx = blockIdx.x * 1024 + t;
    int v = (idx < N_NODES) ? deg[idx] : 0;
    int lane = t & 31, wid = t >> 5;
    int sc = v;
#pragma unroll
    for (int o = 1; o < 32; o <<= 1) {
        int u = __shfl_up_sync(0xFFFFFFFFu, sc, o);
        if (lane >= o) sc += u;
    }
    if (lane == 31) warpsum[wid] = sc;
    __syncthreads();
    if (wid == 0) {
        int s = warpsum[lane];
#pragma unroll
        for (int o = 1; o < 32; o <<= 1) {
            int u = __shfl_up_sync(0xFFFFFFFFu, s, o);
            if (lane >= o) s += u;
        }
        warpsum[lane] = s;
    }
    __syncthreads();
    int base = part[blockIdx.x] + ((wid > 0) ? warpsum[wid - 1] : 0);
    if (idx < N_NODES) offs[idx] = base + sc - v;
}

__global__ void __launch_bounds__(256)
fill_csr_kernel(const int* __restrict__ ei, const int* __restrict__ et,
                const int* __restrict__ offs, const int* __restrict__ epos,
                int* __restrict__ csr) {
    int e = blockIdx.x * blockDim.x + threadIdx.x;
    if (e >= N_EDGES) return;
    int s = ei[e];
    int d = ei[N_EDGES + e];
    int r = et[e];
    csr[offs[d] + epos[e]] = s | (r << 30);
}

// ---------------------------------------------------------------------------
// Layer-1 aggregation (L2 BW floor)
__global__ void __launch_bounds__(256)
agg1_kernel(const float* __restrict__ x,
            const int* __restrict__ offs, const int* __restrict__ deg,
            const int* __restrict__ csr,
            __nv_bfloat16* __restrict__ AGGh, __nv_bfloat16* __restrict__ AGGl) {
    int w = (blockIdx.x * blockDim.x + threadIdx.x) >> 5;
    int lane = threadIdx.x & 31;
    if (w >= N_NODES) return;
    int off = offs[w], dg = deg[w];
    float4 a0 = make_float4(0.f, 0.f, 0.f, 0.f);
    float4 a1 = make_float4(0.f, 0.f, 0.f, 0.f);
    int c0 = 0;
    int j = 0;
    const int col = lane * 4;
    for (; j + 4 <= dg; j += 4) {
        int e0 = csr[off + j], e1 = csr[off + j + 1];
        int e2 = csr[off + j + 2], e3 = csr[off + j + 3];
        float4 v0 = *(const float4*)(x + (size_t)(e0 & 0x3FFFFFFF) * 128 + col);
        float4 v1 = *(const float4*)(x + (size_t)(e1 & 0x3FFFFFFF) * 128 + col);
        float4 v2 = *(const float4*)(x + (size_t)(e2 & 0x3FFFFFFF) * 128 + col);
        float4 v3 = *(const float4*)(x + (size_t)(e3 & 0x3FFFFFFF) * 128 + col);
        if ((e0 >> 30) == 0) { a0.x += v0.x; a0.y += v0.y; a0.z += v0.z; a0.w += v0.w; c0++; }
        else                 { a1.x += v0.x; a1.y += v0.y; a1.z += v0.z; a1.w += v0.w; }
        if ((e1 >> 30) == 0) { a0.x += v1.x; a0.y += v1.y; a0.z += v1.z; a0.w += v1.w; c0++; }
        else                 { a1.x += v1.x; a1.y += v1.y; a1.z += v1.z; a1.w += v1.w; }
        if ((e2 >> 30) == 0) { a0.x += v2.x; a0.y += v2.y; a0.z += v2.z; a0.w += v2.w; c0++; }
        else                 { a1.x += v2.x; a1.y += v2.y; a1.z += v2.z; a1.w += v2.w; }
        if ((e3 >> 30) == 0) { a0.x += v3.x; a0.y += v3.y; a0.z += v3.z; a0.w += v3.w; c0++; }
        else                 { a1.x += v3.x; a1.y += v3.y; a1.z += v3.z; a1.w += v3.w; }
    }
    for (; j < dg; j++) {
        int e0 = csr[off + j];
        float4 v0 = *(const float4*)(x + (size_t)(e0 & 0x3FFFFFFF) * 128 + col);
        if ((e0 >> 30) == 0) { a0.x += v0.x; a0.y += v0.y; a0.z += v0.z; a0.w += v0.w; c0++; }
        else                 { a1.x += v0.x; a1.y += v0.y; a1.z += v0.z; a1.w += v0.w; }
    }
    int c1 = dg - c0;
    float s0 = 1.0f / (float)max(c0, 1);
    float s1 = 1.0f / (float)max(c1, 1);
    a0.x *= s0; a0.y *= s0; a0.z *= s0; a0.w *= s0;
    a1.x *= s1; a1.y *= s1; a1.z *= s1; a1.w *= s1;
    unsigned h0, h1, l0, l1;
    split4(a0, h0, h1, l0, l1);
    *(uint2*)(AGGh + (size_t)w * 256 + col) = make_uint2(h0, h1);
    *(uint2*)(AGGl + (size_t)w * 256 + col) = make_uint2(l0, l1);
    split4(a1, h0, h1, l0, l1);
    *(uint2*)(AGGh + (size_t)w * 256 + 128 + col) = make_uint2(h0, h1);
    *(uint2*)(AGGl + (size_t)w * 256 + 128 + col) = make_uint2(l0, l1);
}

// Layer-2 aggregation + final epilogue
__global__ void __launch_bounds__(256)
agg2_kernel(const float* __restrict__ P,
            const int* __restrict__ offs, const int* __restrict__ deg,
            const int* __restrict__ csr,
            const float* __restrict__ b2, float* __restrict__ out) {
    int w = (blockIdx.x * blockDim.x + threadIdx.x) >> 5;
    int lane = threadIdx.x & 31;
    if (w >= N_NODES) return;
    int off = offs[w], dg = deg[w];
    float2 a0 = make_float2(0.f, 0.f), a1 = make_float2(0.f, 0.f);
    int c0 = 0;
    int j = 0;
    const int col = lane * 2;
    for (; j + 4 <= dg; j += 4) {
        int e0 = csr[off + j], e1 = csr[off + j + 1];
        int e2 = csr[off + j + 2], e3 = csr[off + j + 3];
        float2 v0 = *(const float2*)(P + (size_t)(e0 & 0x3FFFFFFF) * 192 + 64 + (e0 >> 30) * 64 + col);
        float2 v1 = *(const float2*)(P + (size_t)(e1 & 0x3FFFFFFF) * 192 + 64 + (e1 >> 30) * 64 + col);
        float2 v2 = *(const float2*)(P + (size_t)(e2 & 0x3FFFFFFF) * 192 + 64 + (e2 >> 30) * 64 + col);
        float2 v3 = *(const float2*)(P + (size_t)(e3 & 0x3FFFFFFF) * 192 + 64 + (e3 >> 30) * 64 + col);
        if ((e0 >> 30) == 0) { a0.x += v0.x; a0.y += v0.y; c0++; } else { a1.x += v0.x; a1.y += v0.y; }
        if ((e1 >> 30) == 0) { a0.x += v1.x; a0.y += v1.y; c0++; } else { a1.x += v1.x; a1.y += v1.y; }
        if ((e2 >> 30) == 0) { a0.x += v2.x; a0.y += v2.y; c0++; } else { a1.x += v2.x; a1.y += v2.y; }
        if ((e3 >> 30) == 0) { a0.x += v3.x; a0.y += v3.y; c0++; } else { a1.x += v3.x; a1.y += v3.y; }
    }
    for (; j < dg; j++) {
        int e0 = csr[off + j];
        float2 v0 = *(const float2*)(P + (size_t)(e0 & 0x3FFFFFFF) * 192 + 64 + (e0 >> 30) * 64 + col);
        if ((e0 >> 30) == 0) { a0.x += v0.x; a0.y += v0.y; c0++; } else { a1.x += v0.x; a1.y += v0.y; }
    }
    int c1 = dg - c0;
    float s0 = 1.0f / (float)max(c0, 1);
    float s1 = 1.0f / (float)max(c1, 1);
    float2 p0 = *(const float2*)(P + (size_t)w * 192 + col);
    float2 bb = *(const float2*)(b2 + col);
    float2 v;
    v.x = p0.x + a0.x * s0 + a1.x * s1 + bb.x;
    v.y = p0.y + a0.y * s0 + a1.y * s1 + bb.y;
    float ss = v.x * v.x + v.y * v.y;
#pragma unroll
    for (int o = 16; o; o >>= 1) ss += __shfl_xor_sync(0xFFFFFFFFu, ss, o);
    float sc = 1.0f / fmaxf(sqrtf(ss), 1e-12f);
    v.x *= sc; v.y *= sc;
    *(float2*)(out + (size_t)w * 64 + col) = v;
}

// ---------------------------------------------------------------------------
__device__ __forceinline__ void mma_bf16(float* c, const unsigned* a, unsigned b0, unsigned b1) {
    asm volatile(
        "mma.sync.aligned.m16n8k16.row.col.f32.bf16.bf16.f32 "
        "{%0,%1,%2,%3}, {%4,%5,%6,%7}, {%8,%9}, {%0,%1,%2,%3};"
        : "+f"(c[0]), "+f"(c[1]), "+f"(c[2]), "+f"(c[3])
        : "r"(a[0]), "r"(a[1]), "r"(a[2]), "r"(a[3]), "r"(b0), "r"(b1));
}

__device__ __forceinline__ void ldsm4(uint32_t addr, unsigned& r0, unsigned& r1,
                                      unsigned& r2, unsigned& r3) {
    asm volatile("ldmatrix.sync.aligned.m8n8.x4.shared.b16 {%0,%1,%2,%3}, [%4];"
                 : "=r"(r0), "=r"(r1), "=r"(r2), "=r"(r3) : "r"(addr));
}

__device__ __forceinline__ void cp16(void* dst_smem, const void* src) {
    uint32_t d = (uint32_t)__cvta_generic_to_shared(dst_smem);
    asm volatile("cp.async.ca.shared.global [%0], [%1], 16;" :: "r"(d), "l"(src));
}

// ---------------------------------------------------------------------------
// Double-buffered tensor-core GEMM, bf16 3-term split, pure cp.async A path.
// ldw: weight row stride. DUAL: A cols k<128 from Ah/Al (lda), k>=128 from
// Gh/Gl (stride 256). HOUT: pre-split bf16 H (+relu); else fp32 C (grid.y
// slices BN).
template<int BN, int KDIM, int WM, int WN, int MT, int NT, bool DUAL, bool RELU, bool HOUT>
__global__ void __launch_bounds__(256, 2)
gemm_db_kernel(const __nv_bfloat16* __restrict__ Ah,
               const __nv_bfloat16* __restrict__ Al, int lda,
               const __nv_bfloat16* __restrict__ Gh,
               const __nv_bfloat16* __restrict__ Gl,
               const __nv_bfloat16* __restrict__ WT_hi,
               const __nv_bfloat16* __restrict__ WT_lo, int ldw,
               const float* __restrict__ bias,
               float* __restrict__ C, int M, int ldc,
               __nv_bfloat16* __restrict__ Hh,
               __nv_bfloat16* __restrict__ Hl) {
    constexpr int BM = 128, BK = 32, BKP = 40;
    constexpr int ASZ = BM * BKP;
    constexpr int BSZ = BN * BKP;
    constexpr int T = KDIM / BK;

    extern __shared__ __align__(16) char smem_raw[];
    __nv_bfloat16* As_hi[2]; __nv_bfloat16* As_lo[2];
    __nv_bfloat16* Bs_hi[2]; __nv_bfloat16* Bs_lo[2];
    {
        __nv_bfloat16* p = (__nv_bfloat16*)smem_raw;
        As_hi[0] = p;            As_lo[0] = p + ASZ;
        As_hi[1] = p + 2 * ASZ;  As_lo[1] = p + 3 * ASZ;
        p += 4 * ASZ;
        Bs_hi[0] = p;            Bs_lo[0] = p + BSZ;
        Bs_hi[1] = p + 2 * BSZ;  Bs_lo[1] = p + 3 * BSZ;
    }

    const int tid = threadIdx.x;
    const int lane = tid & 31;
    const int warp = tid >> 5;
    const int warpM = warp / WN;
    const int warpN = warp % WN;
    const int m0 = blockIdx.x * BM;
    const int g = lane >> 2;
    const int kq = (lane & 3) * 2;

    const __nv_bfloat16* Wh = WT_hi + (size_t)blockIdx.y * BN * ldw;
    const __nv_bfloat16* Wl = WT_lo + (size_t)blockIdx.y * BN * ldw;

    float acc[MT][NT][4];
#pragma unroll
    for (int i = 0; i < MT; i++)
#pragma unroll
        for (int j = 0; j < NT; j++)
#pragma unroll
            for (int q = 0; q < 4; q++) acc[i][j][q] = 0.f;

    auto loadB = [&](int k0, int stg) {
#pragma unroll
        for (int i = tid; i < BN * 4; i += 256) {
            int n = i >> 2, q = i & 3;
            cp16(Bs_hi[stg] + n * BKP + q * 8, Wh + (size_t)n * ldw + k0 + q * 8);
            cp16(Bs_lo[stg] + n * BKP + q * 8, Wl + (size_t)n * ldw + k0 + q * 8);
        }
    };
    auto loadA = [&](int k0, int stg) {
#pragma unroll
        for (int i = tid; i < BM * 4; i += 256) {
            int row = i >> 2, q = i & 3;
            int m = (m0 + row < M) ? (m0 + row) : (M - 1);
            const __nv_bfloat16 *sh, *sl;
            if (DUAL && k0 >= 128) {
                sh = Gh + (size_t)m * 256 + (k0 - 128) + q * 8;
                sl = Gl + (size_t)m * 256 + (k0 - 128) + q * 8;
            } else {
                sh = Ah + (size_t)m * lda + k0 + q * 8;
                sl = Al + (size_t)m * lda + k0 + q * 8;
            }
            cp16(As_hi[stg] + row * BKP + q * 8, sh);
            cp16(As_lo[stg] + row * BKP + q * 8, sl);
        }
    };

    const int rowA = (lane & 7) + (lane & 8);
    const int colA = (lane & 16) ? 8 : 0;
    const int gB = lane >> 3;
    const int rowB = (lane & 7) + ((gB & 1) ? 8 : 0);
    const int colB = (gB >> 1) * 8;

    uint32_t sAhi[2], sAlo[2], sBhi[2], sBlo[2];
#pragma unroll
    for (int s = 0; s < 2; s++) {
        sAhi[s] = (uint32_t)__cvta_generic_to_shared(As_hi[s]);
        sAlo[s] = (uint32_t)__cvta_generic_to_shared(As_lo[s]);
        sBhi[s] = (uint32_t)__cvta_generic_to_shared(Bs_hi[s]);
        sBlo[s] = (uint32_t)__cvta_generic_to_shared(Bs_lo[s]);
    }

    auto compute = [&](int stg) {
#pragma unroll
        for (int ks = 0; ks < BK; ks += 16) {
            unsigned ah[MT][4], al[MT][4];
#pragma unroll
            for (int mt = 0; mt < MT; mt++) {
                uint32_t off = (uint32_t)(2 * ((warpM * MT * 16 + mt * 16 + rowA) * BKP + ks + colA));
                ldsm4(sAhi[stg] + off, ah[mt][0], ah[mt][1], ah[mt][2], ah[mt][3]);
                ldsm4(sAlo[stg] + off, al[mt][0], al[mt][1], al[mt][2], al[mt][3]);
            }
            unsigned bh0[NT], bh1[NT], bl0[NT], bl1[NT];
#pragma unroll
            for (int np = 0; np < NT / 2; np++) {
                uint32_t off = (uint32_t)(2 * ((warpN * NT * 8 + np * 16 + rowB) * BKP + ks + colB));
                ldsm4(sBhi[stg] + off, bh0[np * 2], bh0[np * 2 + 1], bh1[np * 2], bh1[np * 2 + 1]);
                ldsm4(sBlo[stg] + off, bl0[np * 2], bl0[np * 2 + 1], bl1[np * 2], bl1[np * 2 + 1]);
            }
#pragma unroll
            for (int mt = 0; mt < MT; mt++)
#pragma unroll
                for (int nt = 0; nt < NT; nt++) {
                    mma_bf16(acc[mt][nt], ah[mt], bh0[nt], bh1[nt]);
                    mma_bf16(acc[mt][nt], ah[mt], bl0[nt], bl1[nt]);
                    mma_bf16(acc[mt][nt], al[mt], bh0[nt], bh1[nt]);
                }
        }
    };

    loadB(0, 0);
    loadA(0, 0);
    asm volatile("cp.async.commit_group;\ncp.async.wait_group 0;" ::: "memory");
    __syncthreads();

    for (int t = 0; t < T; t++) {
        int cur = t & 1, nxt = cur ^ 1;
        bool hasNext = (t + 1 < T);
        int k1 = (t + 1) * BK;
        if (hasNext) {
            loadB(k1, nxt);
            loadA(k1, nxt);
        }
        compute(cur);
        asm volatile("cp.async.commit_group;\ncp.async.wait_group 0;" ::: "memory");
        __syncthreads();
    }

#pragma unroll
    for (int nt = 0; nt < NT; nt++) {
        int n = warpN * NT * 8 + nt * 8 + kq;
        float b0 = bias ? bias[n] : 0.f;
        float b1 = bias ? bias[n + 1] : 0.f;
#pragma unroll
        for (int mt = 0; mt < MT; mt++) {
            float* c = acc[mt][nt];
            c[0] += b0; c[1] += b1; c[2] += b0; c[3] += b1;
            if (RELU) {
                c[0] = fmaxf(c[0], 0.f); c[1] = fmaxf(c[1], 0.f);
                c[2] = fmaxf(c[2], 0.f); c[3] = fmaxf(c[3], 0.f);
            }
        }
    }

    if (HOUT) {
#pragma unroll
        for (int mt = 0; mt < MT; mt++) {
            int r0 = m0 + warpM * MT * 16 + mt * 16 + g;
#pragma unroll
            for (int nt = 0; nt < NT; nt++) {
                int n = warpN * NT * 8 + nt * 8 + kq;
                float* c = acc[mt][nt];
                if (r0 < M) {
                    __nv_bfloat16 h0 = __float2bfloat16(c[0]);
                    __nv_bfloat16 h1 = __float2bfloat16(c[1]);
                    *(unsigned*)(Hh + (size_t)r0 * 128 + n) = pack2(h0, h1);
                    *(unsigned*)(Hl + (size_t)r0 * 128 + n) =
                        pack2(__float2bfloat16(c[0] - __bfloat162float(h0)),
                              __float2bfloat16(c[1] - __bfloat162float(h1)));
                }
                if (r0 + 8 < M) {
                    __nv_bfloat16 h2 = __float2bfloat16(c[2]);
                    __nv_bfloat16 h3 = __float2bfloat16(c[3]);
                    *(unsigned*)(Hh + (size_t)(r0 + 8) * 128 + n) = pack2(h2, h3);
                    *(unsigned*)(Hl + (size_t)(r0 + 8) * 128 + n) =
                        pack2(__float2bfloat16(c[2] - __bfloat162float(h2)),
                              __float2bfloat16(c[3] - __bfloat162float(h3)));
                }
            }
        }
    } else {
        float* Cb = C + (size_t)blockIdx.y * BN;
#pragma unroll
        for (int mt = 0; mt < MT; mt++) {
            int r0 = m0 + warpM * MT * 16 + mt * 16 + g;
#pragma unroll
            for (int nt = 0; nt < NT; nt++) {
                int n = warpN * NT * 8 + nt * 8 + kq;
                float* c = acc[mt][nt];
                if (r0 < M)
                    *(float2*)(Cb + (size_t)r0 * ldc + n) = make_float2(c[0], c[1]);
                if (r0 + 8 < M)
                    *(float2*)(Cb + (size_t)(r0 + 8) * ldc + n) = make_float2(c[2], c[3]);
            }
        }
    }
}

// ---------------------------------------------------------------------------
extern "C" void kernel_launch(void* const* d_in, const int* in_sizes, int n_in,
                              void* d_out, int out_size) {
    const float* x       = (const float*)d_in[0];
    const int*   ei      = (const int*)d_in[1];
    const int*   et      = (const int*)d_in[2];
    const float* W1_rel  = (const float*)d_in[3];
    const float* W1_root = (const float*)d_in[4];
    const float* b1      = (const float*)d_in[5];
    const float* W2_rel  = (const float*)d_in[6];
    const float* W2_root = (const float*)d_in[7];
    const float* b2      = (const float*)d_in[8];
    float* out = (float*)d_out;

    float* P;
    __nv_bfloat16 *Xh, *Xl, *Ah, *Al, *Hh, *Hl, *W1Th, *W1Tl, *W2Th, *W2Tl;
    int *deg, *offs, *epos, *part, *csr;
    cudaGetSymbolAddress((void**)&P,    g_P);
    cudaGetSymbolAddress((void**)&Xh,   g_X_hi);
    cudaGetSymbolAddress((void**)&Xl,   g_X_lo);
    cudaGetSymbolAddress((void**)&Ah,   g_AGG_hi);
    cudaGetSymbolAddress((void**)&Al,   g_AGG_lo);
    cudaGetSymbolAddress((void**)&Hh,   g_H_hi);
    cudaGetSymbolAddress((void**)&Hl,   g_H_lo);
    cudaGetSymbolAddress((void**)&W1Th, g_W1T_hi);
    cudaGetSymbolAddress((void**)&W1Tl, g_W1T_lo);
    cudaGetSymbolAddress((void**)&W2Th, g_W2T_hi);
    cudaGetSymbolAddress((void**)&W2Tl, g_W2T_lo);
    cudaGetSymbolAddress((void**)&deg,  g_deg);
    cudaGetSymbolAddress((void**)&offs, g_offs);
    cudaGetSymbolAddress((void**)&epos, g_epos);
    cudaGetSymbolAddress((void**)&part, g_part);
    cudaGetSymbolAddress((void**)&csr,  g_csr);

    const int SM1 = (4 * 128 * 40 + 4 * 128 * 40) * 2;   // 81920 (BN=128)
    const int SM2 = (4 * 128 * 40 + 4 * 96 * 40) * 2;    // 71680 (BN=96)
    auto* k1 = gemm_db_kernel<128, 384, 2, 4, 4, 4, true,  true,  true>;
    auto* k2 = gemm_db_kernel<96,  128, 4, 2, 2, 6, false, false, false>;
    cudaFuncSetAttribute(k1, cudaFuncAttributeMaxDynamicSharedMemorySize, SM1);
    cudaFuncSetAttribute(k2, cudaFuncAttributeMaxDynamicSharedMemorySize, SM2);

    const int TB = 256;
    const int g_prep  = (128 * KTOT + 192 * 128 + TB - 1) / TB;
    const int g_prepx = (N_NODES * 32 + TB - 1) / TB;
    const int g_edge  = (N_EDGES + TB - 1) / TB;
    const int g_agg   = (N_NODES * 32 + TB - 1) / TB;
    const int g_gemm  = (N_NODES + 127) / 128;

    // ---- fork: preps run on a side stream while CSR builds on main ----
    cudaStream_t s1;
    cudaEvent_t ev0, evP;
    cudaStreamCreateWithFlags(&s1, cudaStreamNonBlocking);
    cudaEventCreateWithFlags(&ev0, cudaEventDisableTiming);
    cudaEventCreateWithFlags(&evP, cudaEventDisableTiming);

    cudaEventRecord(ev0, 0);
    cudaStreamWaitEvent(s1, ev0, 0);
    prep_w_kernel<<<g_prep, TB, 0, s1>>>(W1_rel, W1_root, W2_rel, W2_root);
    prep_x_kernel<<<g_prepx, TB, 0, s1>>>(x, Xh, Xl);
    cudaEventRecord(evP, s1);

    // ---- main: CSR build + layer-1 aggregation ----
    cudaMemsetAsync(deg, 0, N_NODES * 4);
    deg_kernel<<<g_edge, TB>>>(ei, deg, epos);
    scan_partial_kernel<<<SCAN_CHUNKS, 1024>>>(deg, part);
    scan_part_kernel<<<1, 128>>>(part);
    scan_final_kernel<<<SCAN_CHUNKS, 1024>>>(deg, part, offs);
    fill_csr_kernel<<<g_edge, TB>>>(ei, et, offs, epos, csr);
    agg1_kernel<<<g_agg, TB>>>(x, offs, deg, csr, Ah, Al);

    // ---- Layer 1 GEMM: H = relu([X|AGG] @ W1 + b1), single pass K=384 ----
    cudaStreamWaitEvent(0, evP, 0);
    k1<<<g_gemm, TB, SM1>>>(Xh, Xl, 128, Ah, Al, W1Th, W1Tl, KTOT, b1,
                            nullptr, N_NODES, 0, Hh, Hl);

    // ---- Layer 2: P = H @ [W2_root|W2_rel0|W2_rel1] (2 slices of 96) ----
    k2<<<dim3(g_gemm, 2), TB, SM2>>>(Hh, Hl, 128, nullptr, nullptr, W2Th, W2Tl, 128,
                                     nullptr, P, N_NODES, 192, nullptr, nullptr);
    agg2_kernel<<<g_agg, TB>>>(P, offs, deg, csr, b2, out);

    cudaEventDestroy(ev0);
    cudaEventDestroy(evP);
    cudaStreamDestroy(s1);
}

// round 17
// speedup vs baseline: 1.4318x; 1.4318x over previous
#include <cuda_runtime.h>
#include <cuda_bf16.h>
#include <cstdint>

#define N_NODES 100000
#define N_EDGES 1600000
#define KTOT 384
#define SCAN_CHUNKS ((N_NODES + 1023) / 1024)   // 98

// ---------------------------------------------------------------------------
// Device-global scratch
__device__ float g_P[(size_t)N_NODES * 192];            // layer-2 transformed
__device__ __nv_bfloat16 g_X_hi[(size_t)N_NODES * 128]; // x pre-split
__device__ __nv_bfloat16 g_X_lo[(size_t)N_NODES * 128];
__device__ __nv_bfloat16 g_AGG_hi[(size_t)N_NODES * 256]; // A0|A1 mean-scaled, pre-split
__device__ __nv_bfloat16 g_AGG_lo[(size_t)N_NODES * 256];
__device__ __nv_bfloat16 g_H_hi[(size_t)N_NODES * 128];
__device__ __nv_bfloat16 g_H_lo[(size_t)N_NODES * 128];
__device__ __nv_bfloat16 g_W1T_hi[128 * KTOT];
__device__ __nv_bfloat16 g_W1T_lo[128 * KTOT];
__device__ __nv_bfloat16 g_W2T_hi[192 * 128];
__device__ __nv_bfloat16 g_W2T_lo[192 * 128];
__device__ int g_deg[N_NODES];
__device__ int g_offs[N_NODES];
__device__ int g_epos[N_EDGES];
__device__ int g_part[SCAN_CHUNKS];
__device__ int g_csr[N_EDGES];                          // src | (rel<<30), grouped by dst

// ---------------------------------------------------------------------------
__device__ __forceinline__ unsigned pack2(__nv_bfloat16 a, __nv_bfloat16 b) {
    union { __nv_bfloat162 v; unsigned u; } c;
    c.v = __halves2bfloat162(a, b);
    return c.u;
}

__device__ __forceinline__ void split4(const float4 v,
                                       unsigned& hi0, unsigned& hi1,
                                       unsigned& lo0, unsigned& lo1) {
    __nv_bfloat16 h0 = __float2bfloat16(v.x), h1 = __float2bfloat16(v.y);
    __nv_bfloat16 h2 = __float2bfloat16(v.z), h3 = __float2bfloat16(v.w);
    __nv_bfloat16 l0 = __float2bfloat16(v.x - __bfloat162float(h0));
    __nv_bfloat16 l1 = __float2bfloat16(v.y - __bfloat162float(h1));
    __nv_bfloat16 l2 = __float2bfloat16(v.z - __bfloat162float(h2));
    __nv_bfloat16 l3 = __float2bfloat16(v.w - __bfloat162float(h3));
    hi0 = pack2(h0, h1); hi1 = pack2(h2, h3);
    lo0 = pack2(l0, l1); lo1 = pack2(l2, l3);
}

// ---------------------------------------------------------------------------
__global__ void __launch_bounds__(256)
prep_w_kernel(const float* __restrict__ W1_rel,
              const float* __restrict__ W1_root,
              const float* __restrict__ W2_rel,
              const float* __restrict__ W2_root) {
    int i = blockIdx.x * blockDim.x + threadIdx.x;
    const int SZ1 = 128 * KTOT;
    const int SZ2 = 192 * 128;
    if (i >= SZ1 + SZ2) return;
    float v;
    __nv_bfloat16 *dh, *dl;
    if (i < SZ1) {
        int n = i / KTOT, k = i % KTOT;
        if (k < 128) v = W1_root[k * 128 + n];
        else {
            int r = (k - 128) >> 7, kk = (k - 128) & 127;
            v = W1_rel[(size_t)r * 128 * 128 + kk * 128 + n];
        }
        dh = g_W1T_hi + i; dl = g_W1T_lo + i;
    } else {
        int j = i - SZ1;
        int n = j / 128, k = j % 128;
        if (n < 64)       v = W2_root[k * 64 + n];
        else if (n < 128) v = W2_rel[(size_t)0 * 128 * 64 + k * 64 + (n - 64)];
        else              v = W2_rel[(size_t)1 * 128 * 64 + k * 64 + (n - 128)];
        dh = g_W2T_hi + j; dl = g_W2T_lo + j;
    }
    __nv_bfloat16 h = __float2bfloat16(v);
    *dh = h;
    *dl = __float2bfloat16(v - __bfloat162float(h));
}

// Pre-split x into bf16 hi/lo
__global__ void __launch_bounds__(256)
prep_x_kernel(const float* __restrict__ x,
              __nv_bfloat16* __restrict__ Xh, __nv_bfloat16* __restrict__ Xl) {
    int i = blockIdx.x * blockDim.x + threadIdx.x;      // over N*32 float4
    if (i >= N_NODES * 32) return;
    float4 v = ((const float4*)x)[i];
    unsigned h0, h1, l0, l1;
    split4(v, h0, h1, l0, l1);
    ((uint2*)Xh)[i] = make_uint2(h0, h1);
    ((uint2*)Xl)[i] = make_uint2(l0, l1);
}

// ---------------------------------------------------------------------------
// CSR construction
__global__ void __launch_bounds__(256)
deg_kernel(const int* __restrict__ ei, int* __restrict__ deg, int* __restrict__ epos) {
    int e = blockIdx.x * blockDim.x + threadIdx.x;
    if (e < N_EDGES) epos[e] = atomicAdd(&deg[ei[N_EDGES + e]], 1);
}

__global__ void __launch_bounds__(1024)
scan_partial_kernel(const int* __restrict__ deg, int* __restrict__ part) {
    __shared__ int red[32];
    int idx = blockIdx.x * 1024 + threadIdx.x;
    int v = (idx < N_NODES) ? deg[idx] : 0;
#pragma unroll
    for (int o = 16; o; o >>= 1) v += __shfl_xor_sync(0xFFFFFFFFu, v, o);
    if ((threadIdx.x & 31) == 0) red[threadIdx.x >> 5] = v;
    __syncthreads();
    if (threadIdx.x < 32) {
        int s = red[threadIdx.x];
#pragma unroll
        for (int o = 16; o; o >>= 1) s += __shfl_xor_sync(0xFFFFFFFFu, s, o);
        if (threadIdx.x == 0) part[blockIdx.x] = s;
    }
}

__global__ void __launch_bounds__(128)
scan_part_kernel(int* __restrict__ part) {
    __shared__ int buf[SCAN_CHUNKS];
    int t = threadIdx.x;
    if (t < SCAN_CHUNKS) buf[t] = part[t];
    __syncthreads();
    if (t == 0) {
        int run = 0;
        for (int i = 0; i < SCAN_CHUNKS; i++) {
            int v = buf[i];
            buf[i] = run;
            run += v;
        }
    }
    __syncthreads();
    if (t < SCAN_CHUNKS) part[t] = buf[t];
}

__global__ void __launch_bounds__(1024)
scan_final_kernel(const int* __restrict__ deg, const int* __restrict__ part,
                  int* __restrict__ offs) {
    __shared__ int warpsum[32];
    int t = threadIdx.x;
    int idx = blockIdx.x * 1024 + t;
    int v = (idx < N_NODES) ? deg[idx] : 0;
    int lane = t & 31, wid = t >> 5;
    int sc = v;
#pragma unroll
    for (int o = 1; o < 32; o <<= 1) {
        int u = __shfl_up_sync(0xFFFFFFFFu, sc, o);
        if (lane >= o) sc += u;
    }
    if (lane == 31) warpsum[wid] = sc;
    __syncthreads();
    if (wid == 0) {
        int s = warpsum[lane];
#pragma unroll
        for (int o = 1; o < 32; o <<= 1) {
            int u = __shfl_up_sync(0xFFFFFFFFu, s, o);
            if (lane >= o) s += u;
        }
        warpsum[lane] = s;
    }
    __syncthreads();
    int base = part[blockIdx.x] + ((wid > 0) ? warpsum[wid - 1] : 0);
    if (idx < N_NODES) offs[idx] = base + sc - v;
}

__global__ void __launch_bounds__(256)
fill_csr_kernel(const int* __restrict__ ei, const int* __restrict__ et,
                const int* __restrict__ offs, const int* __restrict__ epos,
                int* __restrict__ csr) {
    int e = blockIdx.x * blockDim.x + threadIdx.x;
    if (e >= N_EDGES) return;
    int s = ei[e];
    int d = ei[N_EDGES + e];
    int r = et[e];
    csr[offs[d] + epos[e]] = s | (r << 30);
}

// ---------------------------------------------------------------------------
// Layer-1 aggregation (L2 BW floor)
__global__ void __launch_bounds__(256)
agg1_kernel(const float* __restrict__ x,
            const int* __restrict__ offs, const int* __restrict__ deg,
            const int* __restrict__ csr,
            __nv_bfloat16* __restrict__ AGGh, __nv_bfloat16* __restrict__ AGGl) {
    int w = (blockIdx.x * blockDim.x + threadIdx.x) >> 5;
    int lane = threadIdx.x & 31;
    if (w >= N_NODES) return;
    int off = offs[w], dg = deg[w];
    float4 a0 = make_float4(0.f, 0.f, 0.f, 0.f);
    float4 a1 = make_float4(0.f, 0.f, 0.f, 0.f);
    int c0 = 0;
    int j = 0;
    const int col = lane * 4;
    for (; j + 4 <= dg; j += 4) {
        int e0 = csr[off + j], e1 = csr[off + j + 1];
        int e2 = csr[off + j + 2], e3 = csr[off + j + 3];
        float4 v0 = *(const float4*)(x + (size_t)(e0 & 0x3FFFFFFF) * 128 + col);
        float4 v1 = *(const float4*)(x + (size_t)(e1 & 0x3FFFFFFF) * 128 + col);
        float4 v2 = *(const float4*)(x + (size_t)(e2 & 0x3FFFFFFF) * 128 + col);
        float4 v3 = *(const float4*)(x + (size_t)(e3 & 0x3FFFFFFF) * 128 + col);
        if ((e0 >> 30) == 0) { a0.x += v0.x; a0.y += v0.y; a0.z += v0.z; a0.w += v0.w; c0++; }
        else                 { a1.x += v0.x; a1.y += v0.y; a1.z += v0.z; a1.w += v0.w; }
        if ((e1 >> 30) == 0) { a0.x += v1.x; a0.y += v1.y; a0.z += v1.z; a0.w += v1.w; c0++; }
        else                 { a1.x += v1.x; a1.y += v1.y; a1.z += v1.z; a1.w += v1.w; }
        if ((e2 >> 30) == 0) { a0.x += v2.x; a0.y += v2.y; a0.z += v2.z; a0.w += v2.w; c0++; }
        else                 { a1.x += v2.x; a1.y += v2.y; a1.z += v2.z; a1.w += v2.w; }
        if ((e3 >> 30) == 0) { a0.x += v3.x; a0.y += v3.y; a0.z += v3.z; a0.w += v3.w; c0++; }
        else                 { a1.x += v3.x; a1.y += v3.y; a1.z += v3.z; a1.w += v3.w; }
    }
    for (; j < dg; j++) {
        int e0 = csr[off + j];
        float4 v0 = *(const float4*)(x + (size_t)(e0 & 0x3FFFFFFF) * 128 + col);
        if ((e0 >> 30) == 0) { a0.x += v0.x; a0.y += v0.y; a0.z += v0.z; a0.w += v0.w; c0++; }
        else                 { a1.x += v0.x; a1.y += v0.y; a1.z += v0.z; a1.w += v0.w; }
    }
    int c1 = dg - c0;
    float s0 = 1.0f / (float)max(c0, 1);
    float s1 = 1.0f / (float)max(c1, 1);
    a0.x *= s0; a0.y *= s0; a0.z *= s0; a0.w *= s0;
    a1.x *= s1; a1.y *= s1; a1.z *= s1; a1.w *= s1;
    unsigned h0, h1, l0, l1;
    split4(a0, h0, h1, l0, l1);
    *(uint2*)(AGGh + (size_t)w * 256 + col) = make_uint2(h0, h1);
    *(uint2*)(AGGl + (size_t)w * 256 + col) = make_uint2(l0, l1);
    split4(a1, h0, h1, l0, l1);
    *(uint2*)(AGGh + (size_t)w * 256 + 128 + col) = make_uint2(h0, h1);
    *(uint2*)(AGGl + (size_t)w * 256 + 128 + col) = make_uint2(l0, l1);
}

// Layer-2 aggregation + final epilogue
__global__ void __launch_bounds__(256)
agg2_kernel(const float* __restrict__ P,
            const int* __restrict__ offs, const int* __restrict__ deg,
            const int* __restrict__ csr,
            const float* __restrict__ b2, float* __restrict__ out) {
    int w = (blockIdx.x * blockDim.x + threadIdx.x) >> 5;
    int lane = threadIdx.x & 31;
    if (w >= N_NODES) return;
    int off = offs[w], dg = deg[w];
    float2 a0 = make_float2(0.f, 0.f), a1 = make_float2(0.f, 0.f);
    int c0 = 0;
    int j = 0;
    const int col = lane * 2;
    for (; j + 4 <= dg; j += 4) {
        int e0 = csr[off + j], e1 = csr[off + j + 1];
        int e2 = csr[off + j + 2], e3 = csr[off + j + 3];
        float2 v0 = *(const float2*)(P + (size_t)(e0 & 0x3FFFFFFF) * 192 + 64 + (e0 >> 30) * 64 + col);
        float2 v1 = *(const float2*)(P + (size_t)(e1 & 0x3FFFFFFF) * 192 + 64 + (e1 >> 30) * 64 + col);
        float2 v2 = *(const float2*)(P + (size_t)(e2 & 0x3FFFFFFF) * 192 + 64 + (e2 >> 30) * 64 + col);
        float2 v3 = *(const float2*)(P + (size_t)(e3 & 0x3FFFFFFF) * 192 + 64 + (e3 >> 30) * 64 + col);
        if ((e0 >> 30) == 0) { a0.x += v0.x; a0.y += v0.y; c0++; } else { a1.x += v0.x; a1.y += v0.y; }
        if ((e1 >> 30) == 0) { a0.x += v1.x; a0.y += v1.y; c0++; } else { a1.x += v1.x; a1.y += v1.y; }
        if ((e2 >> 30) == 0) { a0.x += v2.x; a0.y += v2.y; c0++; } else { a1.x += v2.x; a1.y += v2.y; }
        if ((e3 >> 30) == 0) { a0.x += v3.x; a0.y += v3.y; c0++; } else { a1.x += v3.x; a1.y += v3.y; }
    }
    for (; j < dg; j++) {
        int e0 = csr[off + j];
        float2 v0 = *(const float2*)(P + (size_t)(e0 & 0x3FFFFFFF) * 192 + 64 + (e0 >> 30) * 64 + col);
        if ((e0 >> 30) == 0) { a0.x += v0.x; a0.y += v0.y; c0++; } else { a1.x += v0.x; a1.y += v0.y; }
    }
    int c1 = dg - c0;
    float s0 = 1.0f / (float)max(c0, 1);
    float s1 = 1.0f / (float)max(c1, 1);
    float2 p0 = *(const float2*)(P + (size_t)w * 192 + col);
    float2 bb = *(const float2*)(b2 + col);
    float2 v;
    v.x = p0.x + a0.x * s0 + a1.x * s1 + bb.x;
    v.y = p0.y + a0.y * s0 + a1.y * s1 + bb.y;
    float ss = v.x * v.x + v.y * v.y;
#pragma unroll
    for (int o = 16; o; o >>= 1) ss += __shfl_xor_sync(0xFFFFFFFFu, ss, o);
    float sc = 1.0f / fmaxf(sqrtf(ss), 1e-12f);
    v.x *= sc; v.y *= sc;
    *(float2*)(out + (size_t)w * 64 + col) = v;
}

// ---------------------------------------------------------------------------
__device__ __forceinline__ void mma_bf16(float* c, const unsigned* a, unsigned b0, unsigned b1) {
    asm volatile(
        "mma.sync.aligned.m16n8k16.row.col.f32.bf16.bf16.f32 "
        "{%0,%1,%2,%3}, {%4,%5,%6,%7}, {%8,%9}, {%0,%1,%2,%3};"
        : "+f"(c[0]), "+f"(c[1]), "+f"(c[2]), "+f"(c[3])
        : "r"(a[0]), "r"(a[1]), "r"(a[2]), "r"(a[3]), "r"(b0), "r"(b1));
}

__device__ __forceinline__ void ldsm4(uint32_t addr, unsigned& r0, unsigned& r1,
                                      unsigned& r2, unsigned& r3) {
    asm volatile("ldmatrix.sync.aligned.m8n8.x4.shared.b16 {%0,%1,%2,%3}, [%4];"
                 : "=r"(r0), "=r"(r1), "=r"(r2), "=r"(r3) : "r"(addr));
}

__device__ __forceinline__ void cp16(void* dst_smem, const void* src) {
    uint32_t d = (uint32_t)__cvta_generic_to_shared(dst_smem);
    asm volatile("cp.async.ca.shared.global [%0], [%1], 16;" :: "r"(d), "l"(src));
}

// ---------------------------------------------------------------------------
// Double-buffered tensor-core GEMM, bf16 3-term split, pure cp.async A path.
// ldw: weight row stride. DUAL: A cols k<128 from Ah/Al (lda), k>=128 from
// Gh/Gl (stride 256). HOUT: pre-split bf16 H (+relu); else fp32 C (grid.y
// slices BN).
template<int BN, int KDIM, int WM, int WN, int MT, int NT, bool DUAL, bool RELU, bool HOUT>
__global__ void __launch_bounds__(256, 2)
gemm_db_kernel(const __nv_bfloat16* __restrict__ Ah,
               const __nv_bfloat16* __restrict__ Al, int lda,
               const __nv_bfloat16* __restrict__ Gh,
               const __nv_bfloat16* __restrict__ Gl,
               const __nv_bfloat16* __restrict__ WT_hi,
               const __nv_bfloat16* __restrict__ WT_lo, int ldw,
               const float* __restrict__ bias,
               float* __restrict__ C, int M, int ldc,
               __nv_bfloat16* __restrict__ Hh,
               __nv_bfloat16* __restrict__ Hl) {
    constexpr int BM = 128, BK = 32, BKP = 40;
    constexpr int ASZ = BM * BKP;
    constexpr int BSZ = BN * BKP;
    constexpr int T = KDIM / BK;

    extern __shared__ __align__(16) char smem_raw[];
    __nv_bfloat16* As_hi[2]; __nv_bfloat16* As_lo[2];
    __nv_bfloat16* Bs_hi[2]; __nv_bfloat16* Bs_lo[2];
    {
        __nv_bfloat16* p = (__nv_bfloat16*)smem_raw;
        As_hi[0] = p;            As_lo[0] = p + ASZ;
        As_hi[1] = p + 2 * ASZ;  As_lo[1] = p + 3 * ASZ;
        p += 4 * ASZ;
        Bs_hi[0] = p;            Bs_lo[0] = p + BSZ;
        Bs_hi[1] = p + 2 * BSZ;  Bs_lo[1] = p + 3 * BSZ;
    }

    const int tid = threadIdx.x;
    const int lane = tid & 31;
    const int warp = tid >> 5;
    const int warpM = warp / WN;
    const int warpN = warp % WN;
    const int m0 = blockIdx.x * BM;
    const int g = lane >> 2;
    const int kq = (lane & 3) * 2;

    const __nv_bfloat16* Wh = WT_hi + (size_t)blockIdx.y * BN * ldw;
    const __nv_bfloat16* Wl = WT_lo + (size_t)blockIdx.y * BN * ldw;

    float acc[MT][NT][4];
#pragma unroll
    for (int i = 0; i < MT; i++)
#pragma unroll
        for (int j = 0; j < NT; j++)
#pragma unroll
            for (int q = 0; q < 4; q++) acc[i][j][q] = 0.f;

    auto loadB = [&](int k0, int stg) {
#pragma unroll
        for (int i = tid; i < BN * 4; i += 256) {
            int n = i >> 2, q = i & 3;
            cp16(Bs_hi[stg] + n * BKP + q * 8, Wh + (size_t)n * ldw + k0 + q * 8);
            cp16(Bs_lo[stg] + n * BKP + q * 8, Wl + (size_t)n * ldw + k0 + q * 8);
        }
    };
    auto loadA = [&](int k0, int stg) {
#pragma unroll
        for (int i = tid; i < BM * 4; i += 256) {
            int row = i >> 2, q = i & 3;
            int m = (m0 + row < M) ? (m0 + row) : (M - 1);
            const __nv_bfloat16 *sh, *sl;
            if (DUAL && k0 >= 128) {
                sh = Gh + (size_t)m * 256 + (k0 - 128) + q * 8;
                sl = Gl + (size_t)m * 256 + (k0 - 128) + q * 8;
            } else {
                sh = Ah + (size_t)m * lda + k0 + q * 8;
                sl = Al + (size_t)m * lda + k0 + q * 8;
            }
            cp16(As_hi[stg] + row * BKP + q * 8, sh);
            cp16(As_lo[stg] + row * BKP + q * 8, sl);
        }
    };

    const int rowA = (lane & 7) + (lane & 8);
    const int colA = (lane & 16) ? 8 : 0;
    const int gB = lane >> 3;
    const int rowB = (lane & 7) + ((gB & 1) ? 8 : 0);
    const int colB = (gB >> 1) * 8;

    uint32_t sAhi[2], sAlo[2], sBhi[2], sBlo[2];
#pragma unroll
    for (int s = 0; s < 2; s++) {
        sAhi[s] = (uint32_t)__cvta_generic_to_shared(As_hi[s]);
        sAlo[s] = (uint32_t)__cvta_generic_to_shared(As_lo[s]);
        sBhi[s] = (uint32_t)__cvta_generic_to_shared(Bs_hi[s]);
        sBlo[s] = (uint32_t)__cvta_generic_to_shared(Bs_lo[s]);
    }

    auto compute = [&](int stg) {
#pragma unroll
        for (int ks = 0; ks < BK; ks += 16) {
            unsigned ah[MT][4], al[MT][4];
#pragma unroll
            for (int mt = 0; mt < MT; mt++) {
                uint32_t off = (uint32_t)(2 * ((warpM * MT * 16 + mt * 16 + rowA) * BKP + ks + colA));
                ldsm4(sAhi[stg] + off, ah[mt][0], ah[mt][1], ah[mt][2], ah[mt][3]);
                ldsm4(sAlo[stg] + off, al[mt][0], al[mt][1], al[mt][2], al[mt][3]);
            }
            unsigned bh0[NT], bh1[NT], bl0[NT], bl1[NT];
#pragma unroll
            for (int np = 0; np < NT / 2; np++) {
                uint32_t off = (uint32_t)(2 * ((warpN * NT * 8 + np * 16 + rowB) * BKP + ks + colB));
                ldsm4(sBhi[stg] + off, bh0[np * 2], bh0[np * 2 + 1], bh1[np * 2], bh1[np * 2 + 1]);
                ldsm4(sBlo[stg] + off, bl0[np * 2], bl0[np * 2 + 1], bl1[np * 2], bl1[np * 2 + 1]);
            }
#pragma unroll
            for (int mt = 0; mt < MT; mt++)
#pragma unroll
                for (int nt = 0; nt < NT; nt++) {
                    mma_bf16(acc[mt][nt], ah[mt], bh0[nt], bh1[nt]);
                    mma_bf16(acc[mt][nt], ah[mt], bl0[nt], bl1[nt]);
                    mma_bf16(acc[mt][nt], al[mt], bh0[nt], bh1[nt]);
                }
        }
    };

    loadB(0, 0);
    loadA(0, 0);
    asm volatile("cp.async.commit_group;\ncp.async.wait_group 0;" ::: "memory");
    __syncthreads();

    for (int t = 0; t < T; t++) {
        int cur = t & 1, nxt = cur ^ 1;
        bool hasNext = (t + 1 < T);
        int k1 = (t + 1) * BK;
        if (hasNext) {
            loadB(k1, nxt);
            loadA(k1, nxt);
        }
        compute(cur);
        asm volatile("cp.async.commit_group;\ncp.async.wait_group 0;" ::: "memory");
        __syncthreads();
    }

#pragma unroll
    for (int nt = 0; nt < NT; nt++) {
        int n = warpN * NT * 8 + nt * 8 + kq;
        float b0 = bias ? bias[n] : 0.f;
        float b1 = bias ? bias[n + 1] : 0.f;
#pragma unroll
        for (int mt = 0; mt < MT; mt++) {
            float* c = acc[mt][nt];
            c[0] += b0; c[1] += b1; c[2] += b0; c[3] += b1;
            if (RELU) {
                c[0] = fmaxf(c[0], 0.f); c[1] = fmaxf(c[1], 0.f);
                c[2] = fmaxf(c[2], 0.f); c[3] = fmaxf(c[3], 0.f);
            }
        }
    }

    if (HOUT) {
#pragma unroll
        for (int mt = 0; mt < MT; mt++) {
            int r0 = m0 + warpM * MT * 16 + mt * 16 + g;
#pragma unroll
            for (int nt = 0; nt < NT; nt++) {
                int n = warpN * NT * 8 + nt * 8 + kq;
                float* c = acc[mt][nt];
                if (r0 < M) {
                    __nv_bfloat16 h0 = __float2bfloat16(c[0]);
                    __nv_bfloat16 h1 = __float2bfloat16(c[1]);
                    *(unsigned*)(Hh + (size_t)r0 * 128 + n) = pack2(h0, h1);
                    *(unsigned*)(Hl + (size_t)r0 * 128 + n) =
                        pack2(__float2bfloat16(c[0] - __bfloat162float(h0)),
                              __float2bfloat16(c[1] - __bfloat162float(h1)));
                }
                if (r0 + 8 < M) {
                    __nv_bfloat16 h2 = __float2bfloat16(c[2]);
                    __nv_bfloat16 h3 = __float2bfloat16(c[3]);
                    *(unsigned*)(Hh + (size_t)(r0 + 8) * 128 + n) = pack2(h2, h3);
                    *(unsigned*)(Hl + (size_t)(r0 + 8) * 128 + n) =
                        pack2(__float2bfloat16(c[2] - __bfloat162float(h2)),
                              __float2bfloat16(c[3] - __bfloat162float(h3)));
                }
            }
        }
    } else {
        float* Cb = C + (size_t)blockIdx.y * BN;
#pragma unroll
        for (int mt = 0; mt < MT; mt++) {
            int r0 = m0 + warpM * MT * 16 + mt * 16 + g;
#pragma unroll
            for (int nt = 0; nt < NT; nt++) {
                int n = warpN * NT * 8 + nt * 8 + kq;
                float* c = acc[mt][nt];
                if (r0 < M)
                    *(float2*)(Cb + (size_t)r0 * ldc + n) = make_float2(c[0], c[1]);
                if (r0 + 8 < M)
                    *(float2*)(Cb + (size_t)(r0 + 8) * ldc + n) = make_float2(c[2], c[3]);
            }
        }
    }
}

// ---------------------------------------------------------------------------
extern "C" void kernel_launch(void* const* d_in, const int* in_sizes, int n_in,
                              void* d_out, int out_size) {
    const float* x       = (const float*)d_in[0];
    const int*   ei      = (const int*)d_in[1];
    const int*   et      = (const int*)d_in[2];
    const float* W1_rel  = (const float*)d_in[3];
    const float* W1_root = (const float*)d_in[4];
    const float* b1      = (const float*)d_in[5];
    const float* W2_rel  = (const float*)d_in[6];
    const float* W2_root = (const float*)d_in[7];
    const float* b2      = (const float*)d_in[8];
    float* out = (float*)d_out;

    float* P;
    __nv_bfloat16 *Xh, *Xl, *Ah, *Al, *Hh, *Hl, *W1Th, *W1Tl, *W2Th, *W2Tl;
    int *deg, *offs, *epos, *part, *csr;
    cudaGetSymbolAddress((void**)&P,    g_P);
    cudaGetSymbolAddress((void**)&Xh,   g_X_hi);
    cudaGetSymbolAddress((void**)&Xl,   g_X_lo);
    cudaGetSymbolAddress((void**)&Ah,   g_AGG_hi);
    cudaGetSymbolAddress((void**)&Al,   g_AGG_lo);
    cudaGetSymbolAddress((void**)&Hh,   g_H_hi);
    cudaGetSymbolAddress((void**)&Hl,   g_H_lo);
    cudaGetSymbolAddress((void**)&W1Th, g_W1T_hi);
    cudaGetSymbolAddress((void**)&W1Tl, g_W1T_lo);
    cudaGetSymbolAddress((void**)&W2Th, g_W2T_hi);
    cudaGetSymbolAddress((void**)&W2Tl, g_W2T_lo);
    cudaGetSymbolAddress((void**)&deg,  g_deg);
    cudaGetSymbolAddress((void**)&offs, g_offs);
    cudaGetSymbolAddress((void**)&epos, g_epos);
    cudaGetSymbolAddress((void**)&part, g_part);
    cudaGetSymbolAddress((void**)&csr,  g_csr);

    const int SM1 = (4 * 128 * 40 + 4 * 128 * 40) * 2;   // 81920 (BN=128)
    const int SM2 = (4 * 128 * 40 + 4 * 64 * 40) * 2;    // 61440 (BN=64)
    auto* k1 = gemm_db_kernel<128, 384, 2, 4, 4, 4, true,  true,  true>;
    auto* k2 = gemm_db_kernel<64,  128, 4, 2, 2, 4, false, false, false>;
    cudaFuncSetAttribute(k1, cudaFuncAttributeMaxDynamicSharedMemorySize, SM1);
    cudaFuncSetAttribute(k2, cudaFuncAttributeMaxDynamicSharedMemorySize, SM2);

    const int TB = 256;
    const int g_prep  = (128 * KTOT + 192 * 128 + TB - 1) / TB;
    const int g_prepx = (N_NODES * 32 + TB - 1) / TB;
    const int g_edge  = (N_EDGES + TB - 1) / TB;
    const int g_agg   = (N_NODES * 32 + TB - 1) / TB;
    const int g_gemm  = (N_NODES + 127) / 128;

    // ---- fork: preps run on a side stream while CSR builds on main ----
    cudaStream_t s1;
    cudaEvent_t ev0, evP;
    cudaStreamCreateWithFlags(&s1, cudaStreamNonBlocking);
    cudaEventCreateWithFlags(&ev0, cudaEventDisableTiming);
    cudaEventCreateWithFlags(&evP, cudaEventDisableTiming);

    cudaEventRecord(ev0, 0);
    cudaStreamWaitEvent(s1, ev0, 0);
    prep_w_kernel<<<g_prep, TB, 0, s1>>>(W1_rel, W1_root, W2_rel, W2_root);
    prep_x_kernel<<<g_prepx, TB, 0, s1>>>(x, Xh, Xl);
    cudaEventRecord(evP, s1);

    // ---- main: CSR build + layer-1 aggregation ----
    cudaMemsetAsync(deg, 0, N_NODES * 4);
    deg_kernel<<<g_edge, TB>>>(ei, deg, epos);
    scan_partial_kernel<<<SCAN_CHUNKS, 1024>>>(deg, part);
    scan_part_kernel<<<1, 128>>>(part);
    scan_final_kernel<<<SCAN_CHUNKS, 1024>>>(deg, part, offs);
    fill_csr_kernel<<<g_edge, TB>>>(ei, et, offs, epos, csr);
    agg1_kernel<<<g_agg, TB>>>(x, offs, deg, csr, Ah, Al);

    // ---- Layer 1 GEMM: H = relu([X|AGG] @ W1 + b1), single pass K=384 ----
    cudaStreamWaitEvent(0, evP, 0);
    k1<<<g_gemm, TB, SM1>>>(Xh, Xl, 128, Ah, Al, W1Th, W1Tl, KTOT, b1,
                            nullptr, N_NODES, 0, Hh, Hl);

    // ---- Layer 2: P = H @ [W2_root|W2_rel0|W2_rel1] (3 slices of 64) ----
    k2<<<dim3(g_gemm, 3), TB, SM2>>>(Hh, Hl, 128, nullptr, nullptr, W2Th, W2Tl, 128,
                                     nullptr, P, N_NODES, 192, nullptr, nullptr);
    agg2_kernel<<<g_agg, TB>>>(P, offs, deg, csr, b2, out);

    cudaEventDestroy(ev0);
    cudaEventDestroy(evP);
    cudaStreamDestroy(s1);
}